// round 5
// baseline (speedup 1.0000x reference)
#include <cuda_runtime.h>
#include <math.h>

#define LL 2048
#define DD 64
#define HH 8

// Per-key folded bias coefficients: [k][8] = {A0,A1,A2, B0,B1,B2, s0_3, s1_3}
__device__ float g_pk[LL * 8];

// ---------------------------------------------------------------------------
// Kernel P: fold d_k_top / d_k_bot / d_k_score into per-key coefficients.
// ---------------------------------------------------------------------------
__global__ void prep_kernel(const float* __restrict__ dkt,
                            const float* __restrict__ dkb,
                            const float* __restrict__ dks) {
    int k = blockIdx.x * blockDim.x + threadIdx.x;
    if (k >= LL) return;
    const float* s0 = dks + k * 8;
    const float* s1 = dks + k * 8 + 4;
#pragma unroll
    for (int f = 0; f < 3; f++) {
        g_pk[k * 8 + f]     = s0[f] + s1[f];
        g_pk[k * 8 + 3 + f] = dkt[k * 3 + f] * s0[f] + dkb[k * 3 + f] * s1[f];
    }
    g_pk[k * 8 + 6] = s0[3];
    g_pk[k * 8 + 7] = s1[3];
}

// ---------------------------------------------------------------------------
// Kernel A: scores = (q.k/8) * softplus(dm.Ww[:,h]) + dm.Wb[:,h]
// Block tile 128(q) x 64(k), 256 threads, 8x4 per-thread tile.
// ---------------------------------------------------------------------------
__global__ __launch_bounds__(256) void scores_kernel(
    const float* __restrict__ q, const float* __restrict__ kmat,
    const float* __restrict__ dq, const float* __restrict__ rt,
    const float* __restrict__ rb, const float* __restrict__ Ww,
    const float* __restrict__ Wb, float* __restrict__ scores) {
    __shared__ __align__(16) float Qs[128][68];
    __shared__ __align__(16) float Ks[64][68];
    __shared__ float Pk[64][8];
    __shared__ float Dq[128][3];

    const int h = blockIdx.y;
    const int qt = blockIdx.x * 128;
    const int t = threadIdx.x;
    const int tx = t & 15;   // 4 keys each:   k-cols tx*4 .. tx*4+3
    const int ty = t >> 4;   // 8 queries each: q-rows ty*8 .. ty*8+7

    const float ww0 = Ww[0 * HH + h], ww1 = Ww[1 * HH + h];
    const float ww2 = Ww[2 * HH + h], ww3 = Ww[3 * HH + h];
    const float wb0 = Wb[0 * HH + h], wb1 = Wb[1 * HH + h];
    const float wb2 = Wb[2 * HH + h], wb3 = Wb[3 * HH + h];

    // Load Q tile (scale 1/sqrt(64) folded in): 128x16 float4
    const float* qbase = q + ((size_t)h * LL + qt) * DD;
    for (int i = t; i < 128 * 16; i += 256) {
        int r = i >> 4, c4 = (i & 15) * 4;
        float4 v4 = *(const float4*)(qbase + r * DD + c4);
        *(float4*)&Qs[r][c4] = make_float4(v4.x * 0.125f, v4.y * 0.125f,
                                           v4.z * 0.125f, v4.w * 0.125f);
    }
    for (int i = t; i < 128 * 3; i += 256) {
        int r = i / 3, f = i % 3;
        Dq[r][f] = dq[(qt + r) * 3 + f];
    }
    __syncthreads();

    float mydq[8][3];
#pragma unroll
    for (int i = 0; i < 8; i++)
#pragma unroll
        for (int f = 0; f < 3; f++) mydq[i][f] = Dq[ty * 8 + i][f];

    for (int kt = 0; kt < LL; kt += 64) {
        __syncthreads();
        const float* kbase = kmat + ((size_t)h * LL + kt) * DD;
        for (int i = t; i < 64 * 16; i += 256) {
            int r = i >> 4, c4 = (i & 15) * 4;
            *(float4*)&Ks[r][c4] = *(const float4*)(kbase + r * DD + c4);
        }
        for (int i = t; i < 64 * 8; i += 256) {
            Pk[i >> 3][i & 7] = g_pk[(size_t)(kt + (i >> 3)) * 8 + (i & 7)];
        }
        __syncthreads();

        float acc[8][4];
#pragma unroll
        for (int i = 0; i < 8; i++)
#pragma unroll
            for (int j = 0; j < 4; j++) acc[i][j] = 0.f;

#pragma unroll 2
        for (int d4 = 0; d4 < DD; d4 += 4) {
            float4 b0 = *(const float4*)&Ks[tx * 4 + 0][d4];
            float4 b1 = *(const float4*)&Ks[tx * 4 + 1][d4];
            float4 b2 = *(const float4*)&Ks[tx * 4 + 2][d4];
            float4 b3 = *(const float4*)&Ks[tx * 4 + 3][d4];
#pragma unroll
            for (int i = 0; i < 8; i++) {
                float4 a = *(const float4*)&Qs[ty * 8 + i][d4];
                acc[i][0] += a.x * b0.x + a.y * b0.y + a.z * b0.z + a.w * b0.w;
                acc[i][1] += a.x * b1.x + a.y * b1.y + a.z * b1.z + a.w * b1.w;
                acc[i][2] += a.x * b2.x + a.y * b2.y + a.z * b2.z + a.w * b2.w;
                acc[i][3] += a.x * b3.x + a.y * b3.y + a.z * b3.z + a.w * b3.w;
            }
        }

        // Epilogue row-by-row (keeps rt/rb register pressure low)
        float pkA[4][3], pkB[4][3], pkS0[4], pkS1[4];
#pragma unroll
        for (int j = 0; j < 4; j++) {
            int kl = tx * 4 + j;
            pkA[j][0] = Pk[kl][0]; pkA[j][1] = Pk[kl][1]; pkA[j][2] = Pk[kl][2];
            pkB[j][0] = Pk[kl][3]; pkB[j][1] = Pk[kl][4]; pkB[j][2] = Pk[kl][5];
            pkS0[j] = Pk[kl][6];   pkS1[j] = Pk[kl][7];
        }

#pragma unroll
        for (int i = 0; i < 8; i++) {
            int qg = qt + ty * 8 + i;
            float4 rt4 = *(const float4*)(rt + (size_t)qg * LL + kt + tx * 4);
            float4 rb4 = *(const float4*)(rb + (size_t)qg * LL + kt + tx * 4);
#pragma unroll
            for (int j = 0; j < 4; j++) {
                float dm0 = mydq[i][0] * pkA[j][0] - pkB[j][0];
                float dm1 = mydq[i][1] * pkA[j][1] - pkB[j][1];
                float dm2 = mydq[i][2] * pkA[j][2] - pkB[j][2];
                float rtv = (&rt4.x)[j];
                float rbv = (&rb4.x)[j];
                float dm3 = rtv * pkS0[j] + rbv * pkS1[j];
                float x  = dm0 * ww0 + dm1 * ww1 + dm2 * ww2 + dm3 * ww3;
                float bb = dm0 * wb0 + dm1 * wb1 + dm2 * wb2 + dm3 * wb3;
                float w = (x > 15.f) ? x : __logf(1.f + __expf(x));
                acc[i][j] = acc[i][j] * w + bb;
            }
            *(float4*)(scores + ((size_t)(h * LL + qg)) * LL + kt + tx * 4) =
                make_float4(acc[i][0], acc[i][1], acc[i][2], acc[i][3]);
        }
    }
}

// ---------------------------------------------------------------------------
// Kernel B: in-place row softmax * c. One block per (h,q) row.
// ---------------------------------------------------------------------------
__global__ __launch_bounds__(256) void softmax_kernel(const float* __restrict__ c,
                                                      float* __restrict__ probs) {
    __shared__ float red[8];
    const size_t row = blockIdx.x;
    float* p = probs + row * LL;
    const int t = threadIdx.x;
    const int lane = t & 31, warp = t >> 5;

    float4 s0 = *(const float4*)(p + t * 4);
    float4 s1 = *(const float4*)(p + 1024 + t * 4);

    float m = fmaxf(fmaxf(fmaxf(s0.x, s0.y), fmaxf(s0.z, s0.w)),
                    fmaxf(fmaxf(s1.x, s1.y), fmaxf(s1.z, s1.w)));
#pragma unroll
    for (int o = 16; o; o >>= 1) m = fmaxf(m, __shfl_xor_sync(0xffffffffu, m, o));
    if (lane == 0) red[warp] = m;
    __syncthreads();
    m = red[0];
#pragma unroll
    for (int i = 1; i < 8; i++) m = fmaxf(m, red[i]);
    __syncthreads();

    float e0x = __expf(s0.x - m), e0y = __expf(s0.y - m);
    float e0z = __expf(s0.z - m), e0w = __expf(s0.w - m);
    float e1x = __expf(s1.x - m), e1y = __expf(s1.y - m);
    float e1z = __expf(s1.z - m), e1w = __expf(s1.w - m);

    float s = e0x + e0y + e0z + e0w + e1x + e1y + e1z + e1w;
#pragma unroll
    for (int o = 16; o; o >>= 1) s += __shfl_xor_sync(0xffffffffu, s, o);
    if (lane == 0) red[warp] = s;
    __syncthreads();
    s = red[0];
#pragma unroll
    for (int i = 1; i < 8; i++) s += red[i];
    float inv = 1.f / s;

    float4 c0 = *(const float4*)(c + t * 4);
    float4 c1 = *(const float4*)(c + 1024 + t * 4);

    *(float4*)(p + t * 4) = make_float4(e0x * inv * c0.x, e0y * inv * c0.y,
                                        e0z * inv * c0.z, e0w * inv * c0.w);
    *(float4*)(p + 1024 + t * 4) = make_float4(e1x * inv * c1.x, e1y * inv * c1.y,
                                               e1z * inv * c1.z, e1w * inv * c1.w);
}

// ---------------------------------------------------------------------------
// Kernel C: out[h,q,d] = sum_k probs[h,q,k] * v[h,k,d].
// Block tile 128(q) x 64(d), 256 threads, 8x4 per-thread tile.
// ---------------------------------------------------------------------------
__global__ __launch_bounds__(256) void pv_kernel(const float* __restrict__ probs,
                                                 const float* __restrict__ v,
                                                 float* __restrict__ out) {
    __shared__ __align__(16) float Ps[128][68];
    __shared__ __align__(16) float Vs[64][68];
    const int h = blockIdx.y;
    const int qt = blockIdx.x * 128;
    const int t = threadIdx.x;
    const int tx = t & 15;   // 4 d-cols each
    const int ty = t >> 4;   // 8 q-rows each

    float acc[8][4];
#pragma unroll
    for (int i = 0; i < 8; i++)
#pragma unroll
        for (int j = 0; j < 4; j++) acc[i][j] = 0.f;

    for (int kt = 0; kt < LL; kt += 64) {
        __syncthreads();
        // Ps: 128 rows x 64 k  (2048 float4)
        for (int i = t; i < 128 * 16; i += 256) {
            int r = i >> 4, c4 = (i & 15) * 4;
            *(float4*)&Ps[r][c4] =
                *(const float4*)(probs + ((size_t)(h * LL + qt + r)) * LL + kt + c4);
        }
        // Vs: 64 k x 64 d (1024 float4)
        for (int i = t; i < 64 * 16; i += 256) {
            int r = i >> 4, c4 = (i & 15) * 4;
            *(float4*)&Vs[r][c4] =
                *(const float4*)(v + ((size_t)(h * LL + kt + r)) * DD + c4);
        }
        __syncthreads();

#pragma unroll 4
        for (int k4 = 0; k4 < 64; k4 += 4) {
            float4 v0 = *(const float4*)&Vs[k4 + 0][tx * 4];
            float4 v1 = *(const float4*)&Vs[k4 + 1][tx * 4];
            float4 v2 = *(const float4*)&Vs[k4 + 2][tx * 4];
            float4 v3 = *(const float4*)&Vs[k4 + 3][tx * 4];
#pragma unroll
            for (int i = 0; i < 8; i++) {
                float4 p = *(const float4*)&Ps[ty * 8 + i][k4];
                acc[i][0] += p.x * v0.x + p.y * v1.x + p.z * v2.x + p.w * v3.x;
                acc[i][1] += p.x * v0.y + p.y * v1.y + p.z * v2.y + p.w * v3.y;
                acc[i][2] += p.x * v0.z + p.y * v1.z + p.z * v2.z + p.w * v3.z;
                acc[i][3] += p.x * v0.w + p.y * v1.w + p.z * v2.w + p.w * v3.w;
            }
        }
    }

#pragma unroll
    for (int i = 0; i < 8; i++) {
        int qg = qt + ty * 8 + i;
        *(float4*)(out + ((size_t)(h * LL + qg)) * DD + tx * 4) =
            make_float4(acc[i][0], acc[i][1], acc[i][2], acc[i][3]);
    }
}

// ---------------------------------------------------------------------------
extern "C" void kernel_launch(void* const* d_in, const int* in_sizes, int n_in,
                              void* d_out, int out_size) {
    const float* q   = (const float*)d_in[0];
    const float* k   = (const float*)d_in[1];
    const float* v   = (const float*)d_in[2];
    const float* c   = (const float*)d_in[3];
    const float* dq  = (const float*)d_in[4];
    const float* dkt = (const float*)d_in[5];
    const float* dkb = (const float*)d_in[6];
    const float* dks = (const float*)d_in[7];
    const float* rt  = (const float*)d_in[8];
    const float* rb  = (const float*)d_in[9];
    const float* Ww  = (const float*)d_in[10];
    const float* Wb  = (const float*)d_in[11];

    float* out   = (float*)d_out;                        // [H, L, D]
    float* probs = (float*)d_out + (size_t)HH * LL * DD; // [H, L, L]

    prep_kernel<<<(LL + 255) / 256, 256>>>(dkt, dkb, dks);

    dim3 gridA(LL / 128, HH);
    scores_kernel<<<gridA, 256>>>(q, k, dq, rt, rb, Ww, Wb, probs);

    softmax_kernel<<<HH * LL, 256>>>(c, probs);

    dim3 gridC(LL / 128, HH);
    pv_kernel<<<gridC, 256>>>(probs, v, out);
}

// round 6
// speedup vs baseline: 1.8034x; 1.8034x over previous
#include <cuda_runtime.h>
#include <cuda_bf16.h>
#include <math.h>
#include <stdint.h>

#define LL 2048
#define DD 64
#define HH 8

// Per-(head,key) folded bias coefficients:
// [0..2]=X0..2  [3]=X3  [4]=X4(rt) [5]=X5(rb)   (x = dq.X012 + X3 + rt*X4 + rb*X5)
// [6..8]=Y0..2  [9]=Y3  [10]=Y4    [11]=Y5      (b = dq.Y012 + Y3 + rt*Y4 + rb*Y5)
__device__ float g_xy[HH][LL][12];

// ---------------------------------------------------------------------------
__device__ __forceinline__ uint32_t smem_u32(const void* p) {
    return (uint32_t)__cvta_generic_to_shared(p);
}
__device__ __forceinline__ void ldsm_x4(uint32_t a, uint32_t& r0, uint32_t& r1,
                                        uint32_t& r2, uint32_t& r3) {
    asm volatile("ldmatrix.sync.aligned.m8n8.x4.shared.b16 {%0,%1,%2,%3}, [%4];"
                 : "=r"(r0), "=r"(r1), "=r"(r2), "=r"(r3) : "r"(a));
}
__device__ __forceinline__ void ldsm_x2(uint32_t a, uint32_t& r0, uint32_t& r1) {
    asm volatile("ldmatrix.sync.aligned.m8n8.x2.shared.b16 {%0,%1}, [%2];"
                 : "=r"(r0), "=r"(r1) : "r"(a));
}
__device__ __forceinline__ void ldsm_x2t(uint32_t a, uint32_t& r0, uint32_t& r1) {
    asm volatile("ldmatrix.sync.aligned.m8n8.x2.trans.shared.b16 {%0,%1}, [%2];"
                 : "=r"(r0), "=r"(r1) : "r"(a));
}
__device__ __forceinline__ void mma16816(float* d, const uint32_t* a, const uint32_t* b) {
    asm volatile(
        "mma.sync.aligned.m16n8k16.row.col.f32.bf16.bf16.f32 "
        "{%0,%1,%2,%3}, {%4,%5,%6,%7}, {%8,%9}, {%0,%1,%2,%3};"
        : "+f"(d[0]), "+f"(d[1]), "+f"(d[2]), "+f"(d[3])
        : "r"(a[0]), "r"(a[1]), "r"(a[2]), "r"(a[3]), "r"(b[0]), "r"(b[1]));
}
__device__ __forceinline__ void split2(float x, __nv_bfloat16& hi, __nv_bfloat16& lo) {
    hi = __float2bfloat16(x);
    lo = __float2bfloat16(x - __bfloat162float(hi));
}
__device__ __forceinline__ float bias_apply(float accv, float d0, float d1, float d2,
                                            float rtv, float rbv,
                                            float4 x0, float4 x1, float4 x2) {
    float x  = d0 * x0.x + d1 * x0.y + d2 * x0.z + x0.w + rtv * x1.x + rbv * x1.y;
    float bb = d0 * x1.z + d1 * x1.w + d2 * x2.x + x2.y + rtv * x2.z + rbv * x2.w;
    float w = (x > 15.f) ? x : __logf(1.f + __expf(x));
    return accv * w + bb;
}

// ---------------------------------------------------------------------------
// Kernel P: per-(h,k) coefficient fold (includes Ww/Wb columns).
// ---------------------------------------------------------------------------
__global__ void prep_kernel(const float* __restrict__ dkt,
                            const float* __restrict__ dkb,
                            const float* __restrict__ dks,
                            const float* __restrict__ Ww,
                            const float* __restrict__ Wb) {
    int idx = blockIdx.x * blockDim.x + threadIdx.x;
    if (idx >= HH * LL) return;
    int h = idx >> 11, k = idx & (LL - 1);
    const float* s0 = dks + k * 8;
    const float* s1 = s0 + 4;
    float* o = g_xy[h][k];
    float X3 = 0.f, Y3 = 0.f;
#pragma unroll
    for (int f = 0; f < 3; f++) {
        float A = s0[f] + s1[f];
        float B = dkt[k * 3 + f] * s0[f] + dkb[k * 3 + f] * s1[f];
        float wwf = Ww[f * HH + h], wbf = Wb[f * HH + h];
        o[f] = A * wwf;
        o[6 + f] = A * wbf;
        X3 -= B * wwf;
        Y3 -= B * wbf;
    }
    float ww3 = Ww[3 * HH + h], wb3 = Wb[3 * HH + h];
    o[3] = X3;            o[9]  = Y3;
    o[4] = s0[3] * ww3;   o[5]  = s1[3] * ww3;
    o[10] = s0[3] * wb3;  o[11] = s1[3] * wb3;
}

// ---------------------------------------------------------------------------
// Kernel A: scores via bf16-split tensor-core QK^T + fused bias epilogue.
// Block: 64(q) x 64(k), 8 warps as 4(m) x 2(n); warp tile 16 x 32.
// ---------------------------------------------------------------------------
__global__ __launch_bounds__(256) void scores_kernel(
    const float* __restrict__ q, const float* __restrict__ kmat,
    const float* __restrict__ dq, const float* __restrict__ rt,
    const float* __restrict__ rb, float* __restrict__ scores) {
    __shared__ __nv_bfloat16 Qh[64][72], Ql[64][72], Kh[64][72], Kl[64][72];
    __shared__ float Xs[64][12];
    __shared__ float Dq[64][4];

    const int h = blockIdx.y, qt = blockIdx.x * 64;
    const int t = threadIdx.x, lane = t & 31, warp = t >> 5;
    const int m0 = (warp >> 1) * 16, n0 = (warp & 1) * 32;

    // Q tile: fp32 -> scaled bf16 hi/lo
    const float* qbase = q + ((size_t)h * LL + qt) * DD;
    for (int i = t; i < 64 * 16; i += 256) {
        int r = i >> 4, c4 = (i & 15) * 4;
        float4 v4 = *(const float4*)(qbase + r * DD + c4);
        float xs[4] = {v4.x * 0.125f, v4.y * 0.125f, v4.z * 0.125f, v4.w * 0.125f};
#pragma unroll
        for (int j = 0; j < 4; j++) split2(xs[j], Qh[r][c4 + j], Ql[r][c4 + j]);
    }
    for (int i = t; i < 64 * 3; i += 256) Dq[i / 3][i % 3] = dq[(qt + i / 3) * 3 + i % 3];
    __syncthreads();

    const int r0l = m0 + (lane >> 2), r1l = r0l + 8;
    const float da0 = Dq[r0l][0], da1 = Dq[r0l][1], da2 = Dq[r0l][2];
    const float db0 = Dq[r1l][0], db1 = Dq[r1l][1], db2 = Dq[r1l][2];
    const int qg0 = qt + r0l, qg1 = qt + r1l;

    for (int kt = 0; kt < LL; kt += 64) {
        __syncthreads();
        const float* kbase = kmat + ((size_t)h * LL + kt) * DD;
        for (int i = t; i < 64 * 16; i += 256) {
            int r = i >> 4, c4 = (i & 15) * 4;
            float4 v4 = *(const float4*)(kbase + r * DD + c4);
            float xs[4] = {v4.x, v4.y, v4.z, v4.w};
#pragma unroll
            for (int j = 0; j < 4; j++) split2(xs[j], Kh[r][c4 + j], Kl[r][c4 + j]);
        }
        for (int i = t; i < 64 * 12; i += 256)
            Xs[i / 12][i % 12] = g_xy[h][kt + i / 12][i % 12];
        __syncthreads();

        float acc[4][4];
#pragma unroll
        for (int nt = 0; nt < 4; nt++)
#pragma unroll
            for (int j = 0; j < 4; j++) acc[nt][j] = 0.f;

#pragma unroll
        for (int s = 0; s < 4; s++) {
            uint32_t ah[4], al[4];
            int ar = m0 + (lane & 15), ac = s * 16 + (lane >> 4) * 8;
            ldsm_x4(smem_u32(&Qh[ar][ac]), ah[0], ah[1], ah[2], ah[3]);
            ldsm_x4(smem_u32(&Ql[ar][ac]), al[0], al[1], al[2], al[3]);
#pragma unroll
            for (int nt = 0; nt < 4; nt++) {
                uint32_t bh[2], bl[2];
                int br = n0 + nt * 8 + (lane & 7);
                int bc = s * 16 + ((lane >> 3) & 1) * 8;
                ldsm_x2(smem_u32(&Kh[br][bc]), bh[0], bh[1]);
                ldsm_x2(smem_u32(&Kl[br][bc]), bl[0], bl[1]);
                mma16816(acc[nt], ah, bh);
                mma16816(acc[nt], ah, bl);
                mma16816(acc[nt], al, bh);
            }
        }

        // Epilogue: bias + softplus gate, write float2 pairs
#pragma unroll
        for (int nt = 0; nt < 4; nt++) {
            int kc = n0 + nt * 8 + (lane & 3) * 2;
            int kg = kt + kc;
            float4 xa0 = *(const float4*)&Xs[kc][0];
            float4 xa1 = *(const float4*)&Xs[kc][4];
            float4 xa2 = *(const float4*)&Xs[kc][8];
            float4 xb0 = *(const float4*)&Xs[kc + 1][0];
            float4 xb1 = *(const float4*)&Xs[kc + 1][4];
            float4 xb2 = *(const float4*)&Xs[kc + 1][8];
            float2 rtA = *(const float2*)(rt + (size_t)qg0 * LL + kg);
            float2 rbA = *(const float2*)(rb + (size_t)qg0 * LL + kg);
            float2 rtB = *(const float2*)(rt + (size_t)qg1 * LL + kg);
            float2 rbB = *(const float2*)(rb + (size_t)qg1 * LL + kg);

            float s00 = bias_apply(acc[nt][0], da0, da1, da2, rtA.x, rbA.x, xa0, xa1, xa2);
            float s01 = bias_apply(acc[nt][1], da0, da1, da2, rtA.y, rbA.y, xb0, xb1, xb2);
            float s10 = bias_apply(acc[nt][2], db0, db1, db2, rtB.x, rbB.x, xa0, xa1, xa2);
            float s11 = bias_apply(acc[nt][3], db0, db1, db2, rtB.y, rbB.y, xb0, xb1, xb2);

            *(float2*)(scores + ((size_t)(h * LL) + qg0) * LL + kg) = make_float2(s00, s01);
            *(float2*)(scores + ((size_t)(h * LL) + qg1) * LL + kg) = make_float2(s10, s11);
        }
    }
}

// ---------------------------------------------------------------------------
// Kernel B: in-place row softmax * c. One block per (h,q) row.
// ---------------------------------------------------------------------------
__global__ __launch_bounds__(256) void softmax_kernel(const float* __restrict__ c,
                                                      float* __restrict__ probs) {
    __shared__ float red[8];
    const size_t row = blockIdx.x;
    float* p = probs + row * LL;
    const int t = threadIdx.x;
    const int lane = t & 31, warp = t >> 5;

    float4 s0 = *(const float4*)(p + t * 4);
    float4 s1 = *(const float4*)(p + 1024 + t * 4);

    float m = fmaxf(fmaxf(fmaxf(s0.x, s0.y), fmaxf(s0.z, s0.w)),
                    fmaxf(fmaxf(s1.x, s1.y), fmaxf(s1.z, s1.w)));
#pragma unroll
    for (int o = 16; o; o >>= 1) m = fmaxf(m, __shfl_xor_sync(0xffffffffu, m, o));
    if (lane == 0) red[warp] = m;
    __syncthreads();
    m = red[0];
#pragma unroll
    for (int i = 1; i < 8; i++) m = fmaxf(m, red[i]);
    __syncthreads();

    float e0x = __expf(s0.x - m), e0y = __expf(s0.y - m);
    float e0z = __expf(s0.z - m), e0w = __expf(s0.w - m);
    float e1x = __expf(s1.x - m), e1y = __expf(s1.y - m);
    float e1z = __expf(s1.z - m), e1w = __expf(s1.w - m);

    float s = e0x + e0y + e0z + e0w + e1x + e1y + e1z + e1w;
#pragma unroll
    for (int o = 16; o; o >>= 1) s += __shfl_xor_sync(0xffffffffu, s, o);
    if (lane == 0) red[warp] = s;
    __syncthreads();
    s = red[0];
#pragma unroll
    for (int i = 1; i < 8; i++) s += red[i];
    float inv = 1.f / s;

    float4 c0 = *(const float4*)(c + t * 4);
    float4 c1 = *(const float4*)(c + 1024 + t * 4);

    *(float4*)(p + t * 4) = make_float4(e0x * inv * c0.x, e0y * inv * c0.y,
                                        e0z * inv * c0.z, e0w * inv * c0.w);
    *(float4*)(p + 1024 + t * 4) = make_float4(e1x * inv * c1.x, e1y * inv * c1.y,
                                               e1z * inv * c1.z, e1w * inv * c1.w);
}

// ---------------------------------------------------------------------------
// Kernel C: out = probs @ V via bf16-split tensor cores.
// Block: 64(q) x 64(d), 8 warps as 4(m) x 2(n); k-reduction over 2048.
// ---------------------------------------------------------------------------
__global__ __launch_bounds__(256) void pv_kernel(const float* __restrict__ probs,
                                                 const float* __restrict__ v,
                                                 float* __restrict__ out) {
    __shared__ __nv_bfloat16 Ph[64][72], Pl[64][72], Vh[64][72], Vl[64][72];
    const int h = blockIdx.y, qt = blockIdx.x * 64;
    const int t = threadIdx.x, lane = t & 31, warp = t >> 5;
    const int m0 = (warp >> 1) * 16, n0 = (warp & 1) * 32;

    float acc[4][4];
#pragma unroll
    for (int nt = 0; nt < 4; nt++)
#pragma unroll
        for (int j = 0; j < 4; j++) acc[nt][j] = 0.f;

    for (int kt = 0; kt < LL; kt += 64) {
        __syncthreads();
        for (int i = t; i < 64 * 16; i += 256) {
            int r = i >> 4, c4 = (i & 15) * 4;
            float4 a = *(const float4*)(probs + ((size_t)(h * LL) + qt + r) * LL + kt + c4);
            float xs[4] = {a.x, a.y, a.z, a.w};
#pragma unroll
            for (int j = 0; j < 4; j++) split2(xs[j], Ph[r][c4 + j], Pl[r][c4 + j]);
            float4 b = *(const float4*)(v + ((size_t)(h * LL) + kt + r) * DD + c4);
            float ys[4] = {b.x, b.y, b.z, b.w};
#pragma unroll
            for (int j = 0; j < 4; j++) split2(ys[j], Vh[r][c4 + j], Vl[r][c4 + j]);
        }
        __syncthreads();

#pragma unroll
        for (int s = 0; s < 4; s++) {
            uint32_t ah[4], al[4];
            int ar = m0 + (lane & 15), ac = s * 16 + (lane >> 4) * 8;
            ldsm_x4(smem_u32(&Ph[ar][ac]), ah[0], ah[1], ah[2], ah[3]);
            ldsm_x4(smem_u32(&Pl[ar][ac]), al[0], al[1], al[2], al[3]);
#pragma unroll
            for (int nt = 0; nt < 4; nt++) {
                uint32_t bh[2], bl[2];
                int vr = s * 16 + (lane & 7) + ((lane >> 3) & 1) * 8;  // key row
                int vc = n0 + nt * 8;                                  // d col
                ldsm_x2t(smem_u32(&Vh[vr][vc]), bh[0], bh[1]);
                ldsm_x2t(smem_u32(&Vl[vr][vc]), bl[0], bl[1]);
                mma16816(acc[nt], ah, bh);
                mma16816(acc[nt], ah, bl);
                mma16816(acc[nt], al, bh);
            }
        }
    }

    const int r0l = m0 + (lane >> 2), r1l = r0l + 8;
#pragma unroll
    for (int nt = 0; nt < 4; nt++) {
        int dc = n0 + nt * 8 + (lane & 3) * 2;
        *(float2*)(out + ((size_t)(h * LL) + qt + r0l) * DD + dc) =
            make_float2(acc[nt][0], acc[nt][1]);
        *(float2*)(out + ((size_t)(h * LL) + qt + r1l) * DD + dc) =
            make_float2(acc[nt][2], acc[nt][3]);
    }
}

// ---------------------------------------------------------------------------
extern "C" void kernel_launch(void* const* d_in, const int* in_sizes, int n_in,
                              void* d_out, int out_size) {
    const float* q   = (const float*)d_in[0];
    const float* k   = (const float*)d_in[1];
    const float* v   = (const float*)d_in[2];
    const float* c   = (const float*)d_in[3];
    const float* dq  = (const float*)d_in[4];
    const float* dkt = (const float*)d_in[5];
    const float* dkb = (const float*)d_in[6];
    const float* dks = (const float*)d_in[7];
    const float* rt  = (const float*)d_in[8];
    const float* rb  = (const float*)d_in[9];
    const float* Ww  = (const float*)d_in[10];
    const float* Wb  = (const float*)d_in[11];

    float* out   = (float*)d_out;                        // [H, L, D]
    float* probs = (float*)d_out + (size_t)HH * LL * DD; // [H, L, L]

    prep_kernel<<<(HH * LL) / 256, 256>>>(dkt, dkb, dks, Ww, Wb);

    dim3 gridA(LL / 64, HH);
    scores_kernel<<<gridA, 256>>>(q, k, dq, rt, rb, probs);

    softmax_kernel<<<HH * LL, 256>>>(c, probs);

    dim3 gridC(LL / 64, HH);
    pv_kernel<<<gridC, 256>>>(probs, v, out);
}

// round 7
// speedup vs baseline: 2.0251x; 1.1229x over previous
#include <cuda_runtime.h>
#include <cuda_bf16.h>
#include <math.h>
#include <stdint.h>

#define LL 2048
#define DD 64
#define HH 8

// Per-(head,key) folded bias coefficients (see prep_kernel)
__device__ float g_xy[HH][LL][12];
// Per-(head,query) softmax stats: (row_max, 1/sum_exp)
__device__ float2 g_stats[HH][LL];
// Preconverted bf16 hi/lo operands
__device__ __nv_bfloat16 gQh[HH * LL * DD], gQl[HH * LL * DD];
__device__ __nv_bfloat16 gKh[HH * LL * DD], gKl[HH * LL * DD];
__device__ __nv_bfloat16 gVh[HH * LL * DD], gVl[HH * LL * DD];

// ---------------------------------------------------------------------------
__device__ __forceinline__ uint32_t smem_u32(const void* p) {
    return (uint32_t)__cvta_generic_to_shared(p);
}
__device__ __forceinline__ void ldsm_x4(uint32_t a, uint32_t& r0, uint32_t& r1,
                                        uint32_t& r2, uint32_t& r3) {
    asm volatile("ldmatrix.sync.aligned.m8n8.x4.shared.b16 {%0,%1,%2,%3}, [%4];"
                 : "=r"(r0), "=r"(r1), "=r"(r2), "=r"(r3) : "r"(a));
}
__device__ __forceinline__ void ldsm_x2(uint32_t a, uint32_t& r0, uint32_t& r1) {
    asm volatile("ldmatrix.sync.aligned.m8n8.x2.shared.b16 {%0,%1}, [%2];"
                 : "=r"(r0), "=r"(r1) : "r"(a));
}
__device__ __forceinline__ void ldsm_x2t(uint32_t a, uint32_t& r0, uint32_t& r1) {
    asm volatile("ldmatrix.sync.aligned.m8n8.x2.trans.shared.b16 {%0,%1}, [%2];"
                 : "=r"(r0), "=r"(r1) : "r"(a));
}
__device__ __forceinline__ void mma16816(float* d, const uint32_t* a, const uint32_t* b) {
    asm volatile(
        "mma.sync.aligned.m16n8k16.row.col.f32.bf16.bf16.f32 "
        "{%0,%1,%2,%3}, {%4,%5,%6,%7}, {%8,%9}, {%0,%1,%2,%3};"
        : "+f"(d[0]), "+f"(d[1]), "+f"(d[2]), "+f"(d[3])
        : "r"(a[0]), "r"(a[1]), "r"(a[2]), "r"(a[3]), "r"(b[0]), "r"(b[1]));
}
__device__ __forceinline__ void split2(float x, __nv_bfloat16& hi, __nv_bfloat16& lo) {
    hi = __float2bfloat16(x);
    lo = __float2bfloat16(x - __bfloat162float(hi));
}
// split+pack two floats -> hi-pair word (ret) and lo-pair word (lo)
__device__ __forceinline__ uint32_t bfpack(float x, float y, uint32_t& lo) {
    __nv_bfloat16 hx, lx, hy, ly;
    split2(x, hx, lx);
    split2(y, hy, ly);
    __nv_bfloat162 H; H.x = hx; H.y = hy;
    __nv_bfloat162 L; L.x = lx; L.y = ly;
    lo = *(uint32_t*)&L;
    return *(uint32_t*)&H;
}
__device__ __forceinline__ float bias_apply(float accv, float d0, float d1, float d2,
                                            float rtv, float rbv,
                                            float4 x0, float4 x1, float4 x2) {
    float x  = d0 * x0.x + d1 * x0.y + d2 * x0.z + x0.w + rtv * x1.x + rbv * x1.y;
    float bb = d0 * x1.z + d1 * x1.w + d2 * x2.x + x2.y + rtv * x2.z + rbv * x2.w;
    float w = (x > 15.f) ? x : __logf(1.f + __expf(x));
    return accv * w + bb;
}

// ---------------------------------------------------------------------------
// Kernel P: per-(h,k) coefficient fold (includes Ww/Wb columns).
// ---------------------------------------------------------------------------
__global__ void prep_kernel(const float* __restrict__ dkt,
                            const float* __restrict__ dkb,
                            const float* __restrict__ dks,
                            const float* __restrict__ Ww,
                            const float* __restrict__ Wb) {
    int idx = blockIdx.x * blockDim.x + threadIdx.x;
    if (idx >= HH * LL) return;
    int h = idx >> 11, k = idx & (LL - 1);
    const float* s0 = dks + k * 8;
    const float* s1 = s0 + 4;
    float* o = g_xy[h][k];
    float X3 = 0.f, Y3 = 0.f;
#pragma unroll
    for (int f = 0; f < 3; f++) {
        float A = s0[f] + s1[f];
        float B = dkt[k * 3 + f] * s0[f] + dkb[k * 3 + f] * s1[f];
        float wwf = Ww[f * HH + h], wbf = Wb[f * HH + h];
        o[f] = A * wwf;
        o[6 + f] = A * wbf;
        X3 -= B * wwf;
        Y3 -= B * wbf;
    }
    float ww3 = Ww[3 * HH + h], wb3 = Wb[3 * HH + h];
    o[3] = X3;            o[9]  = Y3;
    o[4] = s0[3] * ww3;   o[5]  = s1[3] * ww3;
    o[10] = s0[3] * wb3;  o[11] = s1[3] * wb3;
}

// ---------------------------------------------------------------------------
// Kernel Conv: fp32 Q(K,V) -> bf16 hi/lo split arrays (Q scaled by 1/8).
// One float4 per thread.
// ---------------------------------------------------------------------------
__global__ void conv_kernel(const float* __restrict__ q,
                            const float* __restrict__ k,
                            const float* __restrict__ v) {
    size_t base = ((size_t)blockIdx.x * 256 + threadIdx.x) * 4;
    if (base >= (size_t)HH * LL * DD) return;

    float4 a = *(const float4*)(q + base);
    uint32_t l0, l1, h0, h1;
    h0 = bfpack(a.x * 0.125f, a.y * 0.125f, l0);
    h1 = bfpack(a.z * 0.125f, a.w * 0.125f, l1);
    *(uint2*)&gQh[base] = make_uint2(h0, h1);
    *(uint2*)&gQl[base] = make_uint2(l0, l1);

    a = *(const float4*)(k + base);
    h0 = bfpack(a.x, a.y, l0);
    h1 = bfpack(a.z, a.w, l1);
    *(uint2*)&gKh[base] = make_uint2(h0, h1);
    *(uint2*)&gKl[base] = make_uint2(l0, l1);

    a = *(const float4*)(v + base);
    h0 = bfpack(a.x, a.y, l0);
    h1 = bfpack(a.z, a.w, l1);
    *(uint2*)&gVh[base] = make_uint2(h0, h1);
    *(uint2*)&gVl[base] = make_uint2(l0, l1);
}

// ---------------------------------------------------------------------------
// Kernel A: raw scores via bf16-split tensor-core QK^T + fused bias epilogue,
// plus online per-row softmax stats -> g_stats.
// Block: 64(q) x 64(k), 8 warps as 4(m) x 2(n).
// ---------------------------------------------------------------------------
__global__ __launch_bounds__(256) void scores_kernel(
    const float* __restrict__ dq, const float* __restrict__ rt,
    const float* __restrict__ rb, float* __restrict__ scores) {
    __shared__ __nv_bfloat16 Qh[64][72], Ql[64][72], Kh[64][72], Kl[64][72];
    __shared__ float Xs[64][12];
    __shared__ float Dq[64][4];
    __shared__ float SredM[8][16], SredS[8][16];

    const int h = blockIdx.y, qt = blockIdx.x * 64;
    const int t = threadIdx.x, lane = t & 31, warp = t >> 5;
    const int m0 = (warp >> 1) * 16, n0 = (warp & 1) * 32;

    // Q tile from preconverted arrays
    for (int i = t; i < 64 * 8; i += 256) {
        int r = i >> 3, c8 = (i & 7) * 8;
        size_t g = ((size_t)h * LL + qt + r) * DD + c8;
        *(uint4*)&Qh[r][c8] = *(const uint4*)&gQh[g];
        *(uint4*)&Ql[r][c8] = *(const uint4*)&gQl[g];
    }
    for (int i = t; i < 64 * 3; i += 256) Dq[i / 3][i % 3] = dq[(qt + i / 3) * 3 + i % 3];
    __syncthreads();

    const int r0l = m0 + (lane >> 2), r1l = r0l + 8;
    const float da0 = Dq[r0l][0], da1 = Dq[r0l][1], da2 = Dq[r0l][2];
    const float db0 = Dq[r1l][0], db1 = Dq[r1l][1], db2 = Dq[r1l][2];
    const int qg0 = qt + r0l, qg1 = qt + r1l;

    float m0r = -1e30f, s0r = 0.f, m1r = -1e30f, s1r = 0.f;

    for (int kt = 0; kt < LL; kt += 64) {
        __syncthreads();
        for (int i = t; i < 64 * 8; i += 256) {
            int r = i >> 3, c8 = (i & 7) * 8;
            size_t g = ((size_t)h * LL + kt + r) * DD + c8;
            *(uint4*)&Kh[r][c8] = *(const uint4*)&gKh[g];
            *(uint4*)&Kl[r][c8] = *(const uint4*)&gKl[g];
        }
        for (int i = t; i < 64 * 12; i += 256)
            Xs[i / 12][i % 12] = g_xy[h][kt + i / 12][i % 12];
        __syncthreads();

        float acc[4][4];
#pragma unroll
        for (int nt = 0; nt < 4; nt++)
#pragma unroll
            for (int j = 0; j < 4; j++) acc[nt][j] = 0.f;

#pragma unroll
        for (int s = 0; s < 4; s++) {
            uint32_t ah[4], al[4];
            int ar = m0 + (lane & 15), ac = s * 16 + (lane >> 4) * 8;
            ldsm_x4(smem_u32(&Qh[ar][ac]), ah[0], ah[1], ah[2], ah[3]);
            ldsm_x4(smem_u32(&Ql[ar][ac]), al[0], al[1], al[2], al[3]);
#pragma unroll
            for (int nt = 0; nt < 4; nt++) {
                uint32_t bh[2], bl[2];
                int br = n0 + nt * 8 + (lane & 7);
                int bc = s * 16 + ((lane >> 3) & 1) * 8;
                ldsm_x2(smem_u32(&Kh[br][bc]), bh[0], bh[1]);
                ldsm_x2(smem_u32(&Kl[br][bc]), bl[0], bl[1]);
                mma16816(acc[nt], ah, bh);
                mma16816(acc[nt], ah, bl);
                mma16816(acc[nt], al, bh);
            }
        }

        // Epilogue: bias + softplus gate, write, and collect for stats
        float v0[8], v1[8];
#pragma unroll
        for (int nt = 0; nt < 4; nt++) {
            int kc = n0 + nt * 8 + (lane & 3) * 2;
            int kg = kt + kc;
            float4 xa0 = *(const float4*)&Xs[kc][0];
            float4 xa1 = *(const float4*)&Xs[kc][4];
            float4 xa2 = *(const float4*)&Xs[kc][8];
            float4 xb0 = *(const float4*)&Xs[kc + 1][0];
            float4 xb1 = *(const float4*)&Xs[kc + 1][4];
            float4 xb2 = *(const float4*)&Xs[kc + 1][8];
            float2 rtA = *(const float2*)(rt + (size_t)qg0 * LL + kg);
            float2 rbA = *(const float2*)(rb + (size_t)qg0 * LL + kg);
            float2 rtB = *(const float2*)(rt + (size_t)qg1 * LL + kg);
            float2 rbB = *(const float2*)(rb + (size_t)qg1 * LL + kg);

            float s00 = bias_apply(acc[nt][0], da0, da1, da2, rtA.x, rbA.x, xa0, xa1, xa2);
            float s01 = bias_apply(acc[nt][1], da0, da1, da2, rtA.y, rbA.y, xb0, xb1, xb2);
            float s10 = bias_apply(acc[nt][2], db0, db1, db2, rtB.x, rbB.x, xa0, xa1, xa2);
            float s11 = bias_apply(acc[nt][3], db0, db1, db2, rtB.y, rbB.y, xb0, xb1, xb2);

            v0[nt * 2] = s00; v0[nt * 2 + 1] = s01;
            v1[nt * 2] = s10; v1[nt * 2 + 1] = s11;

            *(float2*)(scores + ((size_t)(h * LL) + qg0) * LL + kg) = make_float2(s00, s01);
            *(float2*)(scores + ((size_t)(h * LL) + qg1) * LL + kg) = make_float2(s10, s11);
        }

        // online stats update (tile-batched)
        float tm0 = v0[0], tm1 = v1[0];
#pragma unroll
        for (int j = 1; j < 8; j++) { tm0 = fmaxf(tm0, v0[j]); tm1 = fmaxf(tm1, v1[j]); }
        float nm0 = fmaxf(m0r, tm0), nm1 = fmaxf(m1r, tm1);
        float ad0 = 0.f, ad1 = 0.f;
#pragma unroll
        for (int j = 0; j < 8; j++) {
            ad0 += __expf(v0[j] - nm0);
            ad1 += __expf(v1[j] - nm1);
        }
        s0r = s0r * __expf(m0r - nm0) + ad0; m0r = nm0;
        s1r = s1r * __expf(m1r - nm1) + ad1; m1r = nm1;
    }

    // Reduce stats: across lane&3 group, then across warp pairs
#pragma unroll
    for (int off = 1; off <= 2; off <<= 1) {
        float om = __shfl_xor_sync(0xffffffffu, m0r, off);
        float os = __shfl_xor_sync(0xffffffffu, s0r, off);
        float nm = fmaxf(m0r, om);
        s0r = s0r * __expf(m0r - nm) + os * __expf(om - nm);
        m0r = nm;
        om = __shfl_xor_sync(0xffffffffu, m1r, off);
        os = __shfl_xor_sync(0xffffffffu, s1r, off);
        nm = fmaxf(m1r, om);
        s1r = s1r * __expf(m1r - nm) + os * __expf(om - nm);
        m1r = nm;
    }
    if ((lane & 3) == 0) {
        int lr = lane >> 2;
        SredM[warp][lr] = m0r;     SredS[warp][lr] = s0r;
        SredM[warp][8 + lr] = m1r; SredS[warp][8 + lr] = s1r;
    }
    __syncthreads();
    if (t < 64) {
        int wp = t >> 4, loc = t & 15;
        float mA = SredM[2 * wp][loc], sA = SredS[2 * wp][loc];
        float mB = SredM[2 * wp + 1][loc], sB = SredS[2 * wp + 1][loc];
        float nm = fmaxf(mA, mB);
        float ss = sA * __expf(mA - nm) + sB * __expf(mB - nm);
        g_stats[h][qt + t] = make_float2(nm, 1.f / ss);
    }
}

// ---------------------------------------------------------------------------
// Kernel C: fused softmax + PV. Reads raw scores, writes final probs,
// accumulates out = probs @ V with bf16-split tensor cores.
// ---------------------------------------------------------------------------
__global__ __launch_bounds__(256) void smpv_kernel(const float* __restrict__ c,
                                                   float* __restrict__ probs,
                                                   float* __restrict__ out) {
    __shared__ __nv_bfloat16 Ph[64][72], Pl[64][72], Vh[64][72], Vl[64][72];
    __shared__ float2 St[64];
    const int h = blockIdx.y, qt = blockIdx.x * 64;
    const int t = threadIdx.x, lane = t & 31, warp = t >> 5;
    const int m0 = (warp >> 1) * 16, n0 = (warp & 1) * 32;

    if (t < 64) St[t] = g_stats[h][qt + t];

    float acc[4][4];
#pragma unroll
    for (int nt = 0; nt < 4; nt++)
#pragma unroll
        for (int j = 0; j < 4; j++) acc[nt][j] = 0.f;

    for (int kt = 0; kt < LL; kt += 64) {
        __syncthreads();
        // P: softmax transform + write probs + split to smem
        for (int i = t; i < 64 * 16; i += 256) {
            int r = i >> 4, c4 = (i & 15) * 4;
            float* prow = probs + ((size_t)(h * LL) + qt + r) * LL + kt + c4;
            float4 s4 = *(const float4*)prow;
            float2 st = St[r];
            float4 cc = *(const float4*)(c + kt + c4);
            float p0 = __expf(s4.x - st.x) * st.y * cc.x;
            float p1 = __expf(s4.y - st.x) * st.y * cc.y;
            float p2 = __expf(s4.z - st.x) * st.y * cc.z;
            float p3 = __expf(s4.w - st.x) * st.y * cc.w;
            *(float4*)prow = make_float4(p0, p1, p2, p3);
            uint32_t l0, l1;
            uint32_t h0 = bfpack(p0, p1, l0);
            uint32_t h1 = bfpack(p2, p3, l1);
            *(uint2*)&Ph[r][c4] = make_uint2(h0, h1);
            *(uint2*)&Pl[r][c4] = make_uint2(l0, l1);
        }
        // V from preconverted arrays
        for (int i = t; i < 64 * 8; i += 256) {
            int r = i >> 3, c8 = (i & 7) * 8;
            size_t g = ((size_t)h * LL + kt + r) * DD + c8;
            *(uint4*)&Vh[r][c8] = *(const uint4*)&gVh[g];
            *(uint4*)&Vl[r][c8] = *(const uint4*)&gVl[g];
        }
        __syncthreads();

#pragma unroll
        for (int s = 0; s < 4; s++) {
            uint32_t ah[4], al[4];
            int ar = m0 + (lane & 15), ac = s * 16 + (lane >> 4) * 8;
            ldsm_x4(smem_u32(&Ph[ar][ac]), ah[0], ah[1], ah[2], ah[3]);
            ldsm_x4(smem_u32(&Pl[ar][ac]), al[0], al[1], al[2], al[3]);
#pragma unroll
            for (int nt = 0; nt < 4; nt++) {
                uint32_t bh[2], bl[2];
                int vr = s * 16 + (lane & 7) + ((lane >> 3) & 1) * 8;
                int vc = n0 + nt * 8;
                ldsm_x2t(smem_u32(&Vh[vr][vc]), bh[0], bh[1]);
                ldsm_x2t(smem_u32(&Vl[vr][vc]), bl[0], bl[1]);
                mma16816(acc[nt], ah, bh);
                mma16816(acc[nt], ah, bl);
                mma16816(acc[nt], al, bh);
            }
        }
    }

    const int r0l = m0 + (lane >> 2), r1l = r0l + 8;
#pragma unroll
    for (int nt = 0; nt < 4; nt++) {
        int dc = n0 + nt * 8 + (lane & 3) * 2;
        *(float2*)(out + ((size_t)(h * LL) + qt + r0l) * DD + dc) =
            make_float2(acc[nt][0], acc[nt][1]);
        *(float2*)(out + ((size_t)(h * LL) + qt + r1l) * DD + dc) =
            make_float2(acc[nt][2], acc[nt][3]);
    }
}

// ---------------------------------------------------------------------------
extern "C" void kernel_launch(void* const* d_in, const int* in_sizes, int n_in,
                              void* d_out, int out_size) {
    const float* q   = (const float*)d_in[0];
    const float* k   = (const float*)d_in[1];
    const float* v   = (const float*)d_in[2];
    const float* c   = (const float*)d_in[3];
    const float* dq  = (const float*)d_in[4];
    const float* dkt = (const float*)d_in[5];
    const float* dkb = (const float*)d_in[6];
    const float* dks = (const float*)d_in[7];
    const float* rt  = (const float*)d_in[8];
    const float* rb  = (const float*)d_in[9];
    const float* Ww  = (const float*)d_in[10];
    const float* Wb  = (const float*)d_in[11];

    float* out   = (float*)d_out;                        // [H, L, D]
    float* probs = (float*)d_out + (size_t)HH * LL * DD; // [H, L, L]

    prep_kernel<<<(HH * LL) / 256, 256>>>(dkt, dkb, dks, Ww, Wb);
    conv_kernel<<<(HH * LL * DD) / (256 * 4), 256>>>(q, k, v);

    dim3 grid(LL / 64, HH);
    scores_kernel<<<grid, 256>>>(dq, rt, rb, probs);
    smpv_kernel<<<grid, 256>>>(c, probs, out);
}

// round 10
// speedup vs baseline: 2.7003x; 1.3335x over previous
#include <cuda_runtime.h>
#include <cuda_bf16.h>
#include <math.h>
#include <stdint.h>

#define LL 2048
#define DD 64
#define HH 8

// Per-(head,key) folded bias coefficients (see prep_kernel)
__device__ float g_xy[HH][LL][12];
// Per-(head,query) softmax stats: (row_max, 1/sum_exp)
__device__ float2 g_stats[HH][LL];
// Preconverted bf16 hi/lo operands
__device__ __nv_bfloat16 gQh[HH * LL * DD], gQl[HH * LL * DD];
__device__ __nv_bfloat16 gKh[HH * LL * DD], gKl[HH * LL * DD];
__device__ __nv_bfloat16 gVh[HH * LL * DD], gVl[HH * LL * DD];

// ---------------------------------------------------------------------------
__device__ __forceinline__ uint32_t smem_u32(const void* p) {
    return (uint32_t)__cvta_generic_to_shared(p);
}
__device__ __forceinline__ void cp16(void* s, const void* g) {
    asm volatile("cp.async.cg.shared.global [%0], [%1], 16;" ::
                 "r"(smem_u32(s)), "l"(g));
}
__device__ __forceinline__ void cp_commit() {
    asm volatile("cp.async.commit_group;" ::: "memory");
}
__device__ __forceinline__ void cp_wait1() {
    asm volatile("cp.async.wait_group 1;" ::: "memory");
}
__device__ __forceinline__ void cp_wait0() {
    asm volatile("cp.async.wait_group 0;" ::: "memory");
}
__device__ __forceinline__ void ldsm_x4(uint32_t a, uint32_t& r0, uint32_t& r1,
                                        uint32_t& r2, uint32_t& r3) {
    asm volatile("ldmatrix.sync.aligned.m8n8.x4.shared.b16 {%0,%1,%2,%3}, [%4];"
                 : "=r"(r0), "=r"(r1), "=r"(r2), "=r"(r3) : "r"(a));
}
__device__ __forceinline__ void ldsm_x2(uint32_t a, uint32_t& r0, uint32_t& r1) {
    asm volatile("ldmatrix.sync.aligned.m8n8.x2.shared.b16 {%0,%1}, [%2];"
                 : "=r"(r0), "=r"(r1) : "r"(a));
}
__device__ __forceinline__ void ldsm_x2t(uint32_t a, uint32_t& r0, uint32_t& r1) {
    asm volatile("ldmatrix.sync.aligned.m8n8.x2.trans.shared.b16 {%0,%1}, [%2];"
                 : "=r"(r0), "=r"(r1) : "r"(a));
}
__device__ __forceinline__ void mma16816(float* d, const uint32_t* a, const uint32_t* b) {
    asm volatile(
        "mma.sync.aligned.m16n8k16.row.col.f32.bf16.bf16.f32 "
        "{%0,%1,%2,%3}, {%4,%5,%6,%7}, {%8,%9}, {%0,%1,%2,%3};"
        : "+f"(d[0]), "+f"(d[1]), "+f"(d[2]), "+f"(d[3])
        : "r"(a[0]), "r"(a[1]), "r"(a[2]), "r"(a[3]), "r"(b[0]), "r"(b[1]));
}
__device__ __forceinline__ void split2(float x, __nv_bfloat16& hi, __nv_bfloat16& lo) {
    hi = __float2bfloat16(x);
    lo = __float2bfloat16(x - __bfloat162float(hi));
}
__device__ __forceinline__ uint32_t bfpack(float x, float y, uint32_t& lo) {
    __nv_bfloat16 hx, lx, hy, ly;
    split2(x, hx, lx);
    split2(y, hy, ly);
    __nv_bfloat162 H; H.x = hx; H.y = hy;
    __nv_bfloat162 L; L.x = lx; L.y = ly;
    lo = *(uint32_t*)&L;
    return *(uint32_t*)&H;
}
__device__ __forceinline__ float bias_apply(float accv, float d0, float d1, float d2,
                                            float rtv, float rbv,
                                            float4 x0, float4 x1, float4 x2) {
    float x  = d0 * x0.x + d1 * x0.y + d2 * x0.z + x0.w + rtv * x1.x + rbv * x1.y;
    float bb = d0 * x1.z + d1 * x1.w + d2 * x2.x + x2.y + rtv * x2.z + rbv * x2.w;
    float w = (x > 15.f) ? x : __logf(1.f + __expf(x));
    return accv * w + bb;
}

// ---------------------------------------------------------------------------
// Kernel P: per-(h,k) coefficient fold (includes Ww/Wb columns).
// ---------------------------------------------------------------------------
__global__ void prep_kernel(const float* __restrict__ dkt,
                            const float* __restrict__ dkb,
                            const float* __restrict__ dks,
                            const float* __restrict__ Ww,
                            const float* __restrict__ Wb) {
    int idx = blockIdx.x * blockDim.x + threadIdx.x;
    if (idx >= HH * LL) return;
    int h = idx >> 11, k = idx & (LL - 1);
    const float* s0 = dks + k * 8;
    const float* s1 = s0 + 4;
    float* o = g_xy[h][k];
    float X3 = 0.f, Y3 = 0.f;
#pragma unroll
    for (int f = 0; f < 3; f++) {
        float A = s0[f] + s1[f];
        float B = dkt[k * 3 + f] * s0[f] + dkb[k * 3 + f] * s1[f];
        float wwf = Ww[f * HH + h], wbf = Wb[f * HH + h];
        o[f] = A * wwf;
        o[6 + f] = A * wbf;
        X3 -= B * wwf;
        Y3 -= B * wbf;
    }
    float ww3 = Ww[3 * HH + h], wb3 = Wb[3 * HH + h];
    o[3] = X3;            o[9]  = Y3;
    o[4] = s0[3] * ww3;   o[5]  = s1[3] * ww3;
    o[10] = s0[3] * wb3;  o[11] = s1[3] * wb3;
}

// ---------------------------------------------------------------------------
// Kernel Conv: fp32 Q(K,V) -> bf16 hi/lo split arrays (Q scaled by 1/8).
// ---------------------------------------------------------------------------
__global__ void conv_kernel(const float* __restrict__ q,
                            const float* __restrict__ k,
                            const float* __restrict__ v) {
    size_t base = ((size_t)blockIdx.x * 256 + threadIdx.x) * 4;
    if (base >= (size_t)HH * LL * DD) return;

    float4 a = *(const float4*)(q + base);
    uint32_t l0, l1, h0, h1;
    h0 = bfpack(a.x * 0.125f, a.y * 0.125f, l0);
    h1 = bfpack(a.z * 0.125f, a.w * 0.125f, l1);
    *(uint2*)&gQh[base] = make_uint2(h0, h1);
    *(uint2*)&gQl[base] = make_uint2(l0, l1);

    a = *(const float4*)(k + base);
    h0 = bfpack(a.x, a.y, l0);
    h1 = bfpack(a.z, a.w, l1);
    *(uint2*)&gKh[base] = make_uint2(h0, h1);
    *(uint2*)&gKl[base] = make_uint2(l0, l1);

    a = *(const float4*)(v + base);
    h0 = bfpack(a.x, a.y, l0);
    h1 = bfpack(a.z, a.w, l1);
    *(uint2*)&gVh[base] = make_uint2(h0, h1);
    *(uint2*)&gVl[base] = make_uint2(l0, l1);
}

// ---------------------------------------------------------------------------
// Kernel A: raw scores + online softmax stats. cp.async 2-stage pipeline.
// Block: 64(q) x 32(k-tile), 8 warps as 4(m) x 2(n), warp tile 16x16.
// ---------------------------------------------------------------------------
__global__ __launch_bounds__(256) void scores_kernel(
    const float* __restrict__ dq, const float* __restrict__ rt,
    const float* __restrict__ rb, float* __restrict__ scores) {
    __shared__ __align__(16) __nv_bfloat16 Qh[64][72], Ql[64][72];
    __shared__ __align__(16) __nv_bfloat16 Kh[2][32][72], Kl[2][32][72];
    __shared__ __align__(16) float Xs[2][32][12];
    __shared__ float Dq[64][4];
    __shared__ float SredM[8][16], SredS[8][16];

    const int h = blockIdx.y, qt = blockIdx.x * 64;
    const int t = threadIdx.x, lane = t & 31, warp = t >> 5;
    const int m0 = (warp >> 1) * 16, n0 = (warp & 1) * 16;

    // issue preload of K tile 0
    {
        int r = t >> 3, cc = (t & 7) * 8;
        size_t g = ((size_t)h * LL + 0 + r) * DD + cc;
        cp16(&Kh[0][r][cc], &gKh[g]);
        cp16(&Kl[0][r][cc], &gKl[g]);
        if (t < 96) cp16(&Xs[0][t / 3][(t % 3) * 4], &g_xy[h][t / 3][(t % 3) * 4]);
    }
    cp_commit();

    // Q tile from preconverted arrays (plain loads)
    for (int i = t; i < 64 * 8; i += 256) {
        int r = i >> 3, c8 = (i & 7) * 8;
        size_t g = ((size_t)h * LL + qt + r) * DD + c8;
        *(uint4*)&Qh[r][c8] = *(const uint4*)&gQh[g];
        *(uint4*)&Ql[r][c8] = *(const uint4*)&gQl[g];
    }
    for (int i = t; i < 64 * 3; i += 256) Dq[i / 3][i % 3] = dq[(qt + i / 3) * 3 + i % 3];
    __syncthreads();

    const int r0l = m0 + (lane >> 2), r1l = r0l + 8;
    const float da0 = Dq[r0l][0], da1 = Dq[r0l][1], da2 = Dq[r0l][2];
    const float db0 = Dq[r1l][0], db1 = Dq[r1l][1], db2 = Dq[r1l][2];
    const int qg0 = qt + r0l, qg1 = qt + r1l;

    float m0r = -1e30f, s0r = 0.f, m1r = -1e30f, s1r = 0.f;

    for (int ti = 0; ti < 64; ti++) {
        const int cur = ti & 1, kt = ti * 32;
        if (ti < 63) {
            int nb = cur ^ 1, nkt = kt + 32;
            int r = t >> 3, cc = (t & 7) * 8;
            size_t g = ((size_t)h * LL + nkt + r) * DD + cc;
            cp16(&Kh[nb][r][cc], &gKh[g]);
            cp16(&Kl[nb][r][cc], &gKl[g]);
            if (t < 96) cp16(&Xs[nb][t / 3][(t % 3) * 4], &g_xy[h][nkt + t / 3][(t % 3) * 4]);
            cp_commit();
            cp_wait1();
        } else {
            cp_wait0();
        }
        __syncthreads();

        // prefetch rt/rb for this tile's epilogue
        float2 prtA[2], prbA[2], prtB[2], prbB[2];
#pragma unroll
        for (int nt = 0; nt < 2; nt++) {
            int kg = kt + n0 + nt * 8 + (lane & 3) * 2;
            prtA[nt] = *(const float2*)(rt + (size_t)qg0 * LL + kg);
            prbA[nt] = *(const float2*)(rb + (size_t)qg0 * LL + kg);
            prtB[nt] = *(const float2*)(rt + (size_t)qg1 * LL + kg);
            prbB[nt] = *(const float2*)(rb + (size_t)qg1 * LL + kg);
        }

        float acc[2][4];
#pragma unroll
        for (int nt = 0; nt < 2; nt++)
#pragma unroll
            for (int j = 0; j < 4; j++) acc[nt][j] = 0.f;

#pragma unroll
        for (int s = 0; s < 4; s++) {
            uint32_t ah[4], al[4];
            int ar = m0 + (lane & 15), ac = s * 16 + (lane >> 4) * 8;
            ldsm_x4(smem_u32(&Qh[ar][ac]), ah[0], ah[1], ah[2], ah[3]);
            ldsm_x4(smem_u32(&Ql[ar][ac]), al[0], al[1], al[2], al[3]);
#pragma unroll
            for (int nt = 0; nt < 2; nt++) {
                uint32_t bh[2], bl[2];
                int br = n0 + nt * 8 + (lane & 7);
                int bc = s * 16 + ((lane >> 3) & 1) * 8;
                ldsm_x2(smem_u32(&Kh[cur][br][bc]), bh[0], bh[1]);
                ldsm_x2(smem_u32(&Kl[cur][br][bc]), bl[0], bl[1]);
                mma16816(acc[nt], ah, bh);
                mma16816(acc[nt], ah, bl);
                mma16816(acc[nt], al, bh);
            }
        }

        // Epilogue: bias + softplus gate + write + stats
        float v0[4], v1[4];
#pragma unroll
        for (int nt = 0; nt < 2; nt++) {
            int kc = n0 + nt * 8 + (lane & 3) * 2;
            int kg = kt + kc;
            float4 xa0 = *(const float4*)&Xs[cur][kc][0];
            float4 xa1 = *(const float4*)&Xs[cur][kc][4];
            float4 xa2 = *(const float4*)&Xs[cur][kc][8];
            float4 xb0 = *(const float4*)&Xs[cur][kc + 1][0];
            float4 xb1 = *(const float4*)&Xs[cur][kc + 1][4];
            float4 xb2 = *(const float4*)&Xs[cur][kc + 1][8];

            float s00 = bias_apply(acc[nt][0], da0, da1, da2, prtA[nt].x, prbA[nt].x, xa0, xa1, xa2);
            float s01 = bias_apply(acc[nt][1], da0, da1, da2, prtA[nt].y, prbA[nt].y, xb0, xb1, xb2);
            float s10 = bias_apply(acc[nt][2], db0, db1, db2, prtB[nt].x, prbB[nt].x, xa0, xa1, xa2);
            float s11 = bias_apply(acc[nt][3], db0, db1, db2, prtB[nt].y, prbB[nt].y, xb0, xb1, xb2);

            v0[nt * 2] = s00; v0[nt * 2 + 1] = s01;
            v1[nt * 2] = s10; v1[nt * 2 + 1] = s11;

            *(float2*)(scores + ((size_t)(h * LL) + qg0) * LL + kg) = make_float2(s00, s01);
            *(float2*)(scores + ((size_t)(h * LL) + qg1) * LL + kg) = make_float2(s10, s11);
        }

        float tm0 = fmaxf(fmaxf(v0[0], v0[1]), fmaxf(v0[2], v0[3]));
        float tm1 = fmaxf(fmaxf(v1[0], v1[1]), fmaxf(v1[2], v1[3]));
        float nm0 = fmaxf(m0r, tm0), nm1 = fmaxf(m1r, tm1);
        float ad0 = 0.f, ad1 = 0.f;
#pragma unroll
        for (int j = 0; j < 4; j++) {
            ad0 += __expf(v0[j] - nm0);
            ad1 += __expf(v1[j] - nm1);
        }
        s0r = s0r * __expf(m0r - nm0) + ad0; m0r = nm0;
        s1r = s1r * __expf(m1r - nm1) + ad1; m1r = nm1;

        __syncthreads();
    }

    // Stats reduction: across lane&3, then warp pairs
#pragma unroll
    for (int off = 1; off <= 2; off <<= 1) {
        float om = __shfl_xor_sync(0xffffffffu, m0r, off);
        float os = __shfl_xor_sync(0xffffffffu, s0r, off);
        float nm = fmaxf(m0r, om);
        s0r = s0r * __expf(m0r - nm) + os * __expf(om - nm);
        m0r = nm;
        om = __shfl_xor_sync(0xffffffffu, m1r, off);
        os = __shfl_xor_sync(0xffffffffu, s1r, off);
        nm = fmaxf(m1r, om);
        s1r = s1r * __expf(m1r - nm) + os * __expf(om - nm);
        m1r = nm;
    }
    if ((lane & 3) == 0) {
        int lr = lane >> 2;
        SredM[warp][lr] = m0r;     SredS[warp][lr] = s0r;
        SredM[warp][8 + lr] = m1r; SredS[warp][8 + lr] = s1r;
    }
    __syncthreads();
    if (t < 64) {
        int wp = t >> 4, loc = t & 15;
        float mA = SredM[2 * wp][loc], sA = SredS[2 * wp][loc];
        float mB = SredM[2 * wp + 1][loc], sB = SredS[2 * wp + 1][loc];
        float nm = fmaxf(mA, mB);
        float ss = sA * __expf(mA - nm) + sB * __expf(mB - nm);
        g_stats[h][qt + t] = make_float2(nm, 1.f / ss);
    }
}

// ---------------------------------------------------------------------------
// Kernel C: fused softmax + PV, P entirely in registers.
// Block: 128(q) x 64(d), 8 warps each owning m16 x n64; k-tiles of 64 with
// cp.async double-buffered V and register-prefetched scores.
// ---------------------------------------------------------------------------
__global__ __launch_bounds__(256) void smpv_kernel(const float* __restrict__ c,
                                                   float* __restrict__ probs,
                                                   float* __restrict__ out) {
    __shared__ __align__(16) __nv_bfloat16 Vh[2][64][72], Vl[2][64][72];
    __shared__ __align__(16) float Cs[2048];

    const int h = blockIdx.y, qt = blockIdx.x * 128;
    const int t = threadIdx.x, lane = t & 31, warp = t >> 5;
    const int c0 = (lane & 3) * 2;
    const int r0 = qt + warp * 16 + (lane >> 2);

    float* sp0 = probs + ((size_t)h * LL + r0) * LL;
    float* sp1 = sp0 + 8 * LL;  // row r0+8

    const float2 st0 = g_stats[h][r0];
    const float2 st1 = g_stats[h][r0 + 8];

    // V tile 0 preload: 64 rows x 64 cols = 512 cp16 per array
#pragma unroll
    for (int j = 0; j < 2; j++) {
        int i = t + j * 256;
        int r = i >> 3, ce = (i & 7) * 8;
        size_t g = ((size_t)h * LL + r) * DD + ce;
        cp16(&Vh[0][r][ce], &gVh[g]);
        cp16(&Vl[0][r][ce], &gVl[g]);
    }
    cp_commit();

    // c -> smem
    for (int i = t; i < 512; i += 256)
        *(float4*)&Cs[i * 4] = *(const float4*)(c + i * 4);

    // prefetch scores tile 0
    float2 pre[16];
#pragma unroll
    for (int s = 0; s < 4; s++) {
        int col = s * 16 + c0;
        pre[s * 4 + 0] = *(const float2*)(sp0 + col);
        pre[s * 4 + 1] = *(const float2*)(sp1 + col);
        pre[s * 4 + 2] = *(const float2*)(sp0 + col + 8);
        pre[s * 4 + 3] = *(const float2*)(sp1 + col + 8);
    }

    float acc[8][4];
#pragma unroll
    for (int nt = 0; nt < 8; nt++)
#pragma unroll
        for (int j = 0; j < 4; j++) acc[nt][j] = 0.f;

    for (int ti = 0; ti < 32; ti++) {
        const int cur = ti & 1, kt = ti * 64;
        if (ti < 31) {
            int nb = cur ^ 1, nkt = kt + 64;
#pragma unroll
            for (int j = 0; j < 2; j++) {
                int i = t + j * 256;
                int r = i >> 3, ce = (i & 7) * 8;
                size_t g = ((size_t)h * LL + nkt + r) * DD + ce;
                cp16(&Vh[nb][r][ce], &gVh[g]);
                cp16(&Vl[nb][r][ce], &gVl[g]);
            }
            cp_commit();
            cp_wait1();
        } else {
            cp_wait0();
        }
        __syncthreads();

        // transform prefetched scores -> probs writes + A fragments
        uint32_t AH[4][4], AL[4][4];
#pragma unroll
        for (int s = 0; s < 4; s++) {
            int col = kt + s * 16 + c0;
            float2 cA = *(const float2*)&Cs[col];
            float2 cB = *(const float2*)&Cs[col + 8];
            float p00 = __expf(pre[s * 4 + 0].x - st0.x) * st0.y * cA.x;
            float p01 = __expf(pre[s * 4 + 0].y - st0.x) * st0.y * cA.y;
            float p10 = __expf(pre[s * 4 + 1].x - st1.x) * st1.y * cA.x;
            float p11 = __expf(pre[s * 4 + 1].y - st1.x) * st1.y * cA.y;
            float p20 = __expf(pre[s * 4 + 2].x - st0.x) * st0.y * cB.x;
            float p21 = __expf(pre[s * 4 + 2].y - st0.x) * st0.y * cB.y;
            float p30 = __expf(pre[s * 4 + 3].x - st1.x) * st1.y * cB.x;
            float p31 = __expf(pre[s * 4 + 3].y - st1.x) * st1.y * cB.y;

            *(float2*)(sp0 + col)     = make_float2(p00, p01);
            *(float2*)(sp1 + col)     = make_float2(p10, p11);
            *(float2*)(sp0 + col + 8) = make_float2(p20, p21);
            *(float2*)(sp1 + col + 8) = make_float2(p30, p31);

            AH[s][0] = bfpack(p00, p01, AL[s][0]);
            AH[s][1] = bfpack(p10, p11, AL[s][1]);
            AH[s][2] = bfpack(p20, p21, AL[s][2]);
            AH[s][3] = bfpack(p30, p31, AL[s][3]);
        }

        // prefetch scores for next tile (hidden under MMAs)
        if (ti < 31) {
            int nkt = kt + 64;
#pragma unroll
            for (int s = 0; s < 4; s++) {
                int col = nkt + s * 16 + c0;
                pre[s * 4 + 0] = *(const float2*)(sp0 + col);
                pre[s * 4 + 1] = *(const float2*)(sp1 + col);
                pre[s * 4 + 2] = *(const float2*)(sp0 + col + 8);
                pre[s * 4 + 3] = *(const float2*)(sp1 + col + 8);
            }
        }

        // MMAs: m16 x n64 per warp
#pragma unroll
        for (int s = 0; s < 4; s++) {
            int vr = s * 16 + (lane & 7) + ((lane >> 3) & 1) * 8;
#pragma unroll
            for (int nt = 0; nt < 8; nt++) {
                uint32_t bh[2], bl[2];
                int vc = nt * 8;
                ldsm_x2t(smem_u32(&Vh[cur][vr][vc]), bh[0], bh[1]);
                ldsm_x2t(smem_u32(&Vl[cur][vr][vc]), bl[0], bl[1]);
                mma16816(acc[nt], AH[s], bh);
                mma16816(acc[nt], AH[s], bl);
                mma16816(acc[nt], AL[s], bh);
            }
        }
        __syncthreads();
    }

    // Output: 16 rows x 64 cols per warp
#pragma unroll
    for (int nt = 0; nt < 8; nt++) {
        int dc = nt * 8 + c0;
        *(float2*)(out + ((size_t)h * LL + r0) * DD + dc) =
            make_float2(acc[nt][0], acc[nt][1]);
        *(float2*)(out + ((size_t)h * LL + r0 + 8) * DD + dc) =
            make_float2(acc[nt][2], acc[nt][3]);
    }
}

// ---------------------------------------------------------------------------
extern "C" void kernel_launch(void* const* d_in, const int* in_sizes, int n_in,
                              void* d_out, int out_size) {
    const float* q   = (const float*)d_in[0];
    const float* k   = (const float*)d_in[1];
    const float* v   = (const float*)d_in[2];
    const float* c   = (const float*)d_in[3];
    const float* dq  = (const float*)d_in[4];
    const float* dkt = (const float*)d_in[5];
    const float* dkb = (const float*)d_in[6];
    const float* dks = (const float*)d_in[7];
    const float* rt  = (const float*)d_in[8];
    const float* rb  = (const float*)d_in[9];
    const float* Ww  = (const float*)d_in[10];
    const float* Wb  = (const float*)d_in[11];

    float* out   = (float*)d_out;                        // [H, L, D]
    float* probs = (float*)d_out + (size_t)HH * LL * DD; // [H, L, L]

    prep_kernel<<<(HH * LL) / 256, 256>>>(dkt, dkb, dks, Ww, Wb);
    conv_kernel<<<(HH * LL * DD) / (256 * 4), 256>>>(q, k, v);

    dim3 gridA(LL / 64, HH);
    scores_kernel<<<gridA, 256>>>(dq, rt, rb, probs);

    dim3 gridC(LL / 128, HH);
    smpv_kernel<<<gridC, 256>>>(c, probs, out);
}